// round 1
// baseline (speedup 1.0000x reference)
#include <cuda_runtime.h>
#include <math.h>

#define NB 20
#define NC 256
#define HW 4096
#define NCHUNK 10
#define QMAXF 255.0f

// ---------------- device scratch (no allocations allowed) ----------------
__device__ float g_bc_min[NB * NC];
__device__ float g_bc_max[NB * NC];
__device__ float g_bc_sum[NB * NC];
__device__ float g_sq[2];        // [0]=scale, [1]=zero_point (float)
__device__ float g_rs[NC];       // 1 / (mean_topk + 1e-7)
__device__ float g_qw[NC];       // quantized weight
__device__ float g_qb[NC];       // quantized bias
__device__ float g_ca[NC];       // out = fq(x)*ca + cb
__device__ float g_cb[NC];

// fake_quant forward with IEEE division (matches JAX regardless of fast-math flags)
__device__ __forceinline__ float fq1(float x, float s, float zp) {
    float v = __fdiv_rn(x, s) + zp;
    v = fminf(fmaxf(v, 0.0f), QMAXF);
    v = rintf(v);                 // round-half-even == jnp.round
    return (v - zp) * s;
}

// ---------------- K1: per-(b,c) raw min/max over 4096 spatial ----------------
__global__ void k_minmax(const float* __restrict__ x) {
    const int bc = blockIdx.x;
    const float4* p = reinterpret_cast<const float4*>(x) + (size_t)bc * (HW / 4);
    float mn = INFINITY, mx = -INFINITY;
    #pragma unroll 4
    for (int i = threadIdx.x; i < HW / 4; i += 256) {
        float4 v = p[i];
        mn = fminf(mn, fminf(fminf(v.x, v.y), fminf(v.z, v.w)));
        mx = fmaxf(mx, fmaxf(fmaxf(v.x, v.y), fmaxf(v.z, v.w)));
    }
    #pragma unroll
    for (int o = 16; o > 0; o >>= 1) {
        mn = fminf(mn, __shfl_xor_sync(0xffffffffu, mn, o));
        mx = fmaxf(mx, __shfl_xor_sync(0xffffffffu, mx, o));
    }
    __shared__ float smn[8], smx[8];
    int wr = threadIdx.x >> 5, ln = threadIdx.x & 31;
    if (ln == 0) { smn[wr] = mn; smx[wr] = mx; }
    __syncthreads();
    if (threadIdx.x == 0) {
        float a = smn[0], b = smx[0];
        #pragma unroll
        for (int i = 1; i < 8; i++) { a = fminf(a, smn[i]); b = fmaxf(b, smx[i]); }
        g_bc_min[bc] = a;
        g_bc_max[bc] = b;
    }
}

// ---------------- K2: scalars, chunk ranges, weight/bias quant (1 block, 256 thr) -------
__global__ void k_stats(const float* __restrict__ w, const float* __restrict__ bias) {
    const int t = threadIdx.x;
    __shared__ float sh_smin[NB], sh_smax[NB];
    __shared__ float sh_s, sh_zp, sh_wmin, sh_wmax, sh_bsum;

    // per-sample min/max over all (c) — threads 0..19, 256 scalar loads each
    if (t < NB) {
        float mn = INFINITY, mx = -INFINITY;
        for (int c = 0; c < NC; c++) {
            mn = fminf(mn, g_bc_min[t * NC + c]);
            mx = fmaxf(mx, g_bc_max[t * NC + c]);
        }
        sh_smin[t] = mn; sh_smax[t] = mx;
    }
    __syncthreads();
    if (t == 0) {
        float a = 0.f, b = 0.f;
        for (int i = 0; i < NB; i++) { a += sh_smin[i]; b += sh_smax[i]; }
        float min_v = a / (float)NB, max_v = b / (float)NB;
        float s = (max_v - min_v) / QMAXF;
        if (s == 0.0f) s = 1.0f;
        float zp = truncf(fminf(fmaxf(__fdiv_rn(-min_v, s), 0.0f), QMAXF));
        sh_s = s; sh_zp = zp;
        g_sq[0] = s; g_sq[1] = zp;
    }
    __syncthreads();
    const float s = sh_s, zp = sh_zp;

    // chunk ranges per channel: chunk k = batches {2k, 2k+1}; fq is monotone,
    // so chunk min/max of xq = fq(chunk min/max of raw x).
    {
        const float cst = (float)(0.5 * 0.35 * (1.0 + sqrt(M_PI * log(4.0)))
                                  / sqrt(2.0 * log(8192.0)));   // n = N/NUM_CHUNKS = 8192
        float csum = 0.f;
        #pragma unroll
        for (int k = 0; k < NCHUNK; k++) {
            float mn = fminf(g_bc_min[(2 * k) * NC + t], g_bc_min[(2 * k + 1) * NC + t]);
            float mx = fmaxf(g_bc_max[(2 * k) * NC + t], g_bc_max[(2 * k + 1) * NC + t]);
            csum += (fq1(mx, s, zp) - fq1(mn, s, zp)) * cst;
        }
        g_rs[t] = __fdiv_rn(1.0f, csum / (float)NCHUNK + 1e-7f);
    }

    // weight min/max + bias sum (256 elements, one per thread)
    float wv = w[t], bv = bias[t];
    float wmn = wv, wmx = wv, bs = bv;
    #pragma unroll
    for (int o = 16; o > 0; o >>= 1) {
        wmn = fminf(wmn, __shfl_xor_sync(0xffffffffu, wmn, o));
        wmx = fmaxf(wmx, __shfl_xor_sync(0xffffffffu, wmx, o));
        bs += __shfl_xor_sync(0xffffffffu, bs, o);
    }
    __shared__ float swmn[8], swmx[8], sbs[8];
    int wr = t >> 5, ln = t & 31;
    if (ln == 0) { swmn[wr] = wmn; swmx[wr] = wmx; sbs[wr] = bs; }
    __syncthreads();
    if (t == 0) {
        float a = swmn[0], b = swmx[0], c = sbs[0];
        #pragma unroll
        for (int i = 1; i < 8; i++) { a = fminf(a, swmn[i]); b = fmaxf(b, swmx[i]); c += sbs[i]; }
        sh_wmin = a; sh_wmax = b; sh_bsum = c;
    }
    __syncthreads();

    // quantized weight (explicit min/max)
    float ws = (sh_wmax - sh_wmin) / QMAXF;
    if (ws == 0.0f) ws = 1.0f;
    float wzp = truncf(fminf(fmaxf(__fdiv_rn(-sh_wmin, ws), 0.0f), QMAXF));
    g_qw[t] = (rintf(fminf(fmaxf(__fdiv_rn(wv, ws) + wzp, 0.0f), QMAXF)) - wzp) * ws;

    // quantized bias: min==max==bias.mean() -> scale=0 -> scale=1 branch
    float bmean = sh_bsum / (float)NC;
    float bzp = truncf(fminf(fmaxf(-bmean, 0.0f), QMAXF));
    g_qb[t] = rintf(fminf(fmaxf(bv + bzp, 0.0f), QMAXF)) - bzp;
}

// ---------------- K3: per-(b,c) sum of fq(x) ----------------
__global__ void k_sum(const float* __restrict__ x) {
    const int bc = blockIdx.x;
    const float s = g_sq[0], zp = g_sq[1];
    const float4* p = reinterpret_cast<const float4*>(x) + (size_t)bc * (HW / 4);
    float acc = 0.f;
    #pragma unroll 4
    for (int i = threadIdx.x; i < HW / 4; i += 256) {
        float4 v = p[i];
        acc += fq1(v.x, s, zp) + fq1(v.y, s, zp) + fq1(v.z, s, zp) + fq1(v.w, s, zp);
    }
    #pragma unroll
    for (int o = 16; o > 0; o >>= 1) acc += __shfl_xor_sync(0xffffffffu, acc, o);
    __shared__ float sm[8];
    int wr = threadIdx.x >> 5, ln = threadIdx.x & 31;
    if (ln == 0) sm[wr] = acc;
    __syncthreads();
    if (threadIdx.x == 0) {
        float a = 0.f;
        #pragma unroll
        for (int i = 0; i < 8; i++) a += sm[i];
        g_bc_sum[bc] = a;
    }
}

// ---------------- K4: per-channel coefficients (1 block, 256 thr) ----------------
__global__ void k_coef() {
    const int c = threadIdx.x;
    float acc = 0.f;
    // mean(-1) over HW then mean(0) over B, matching reference order
    for (int b = 0; b < NB; b++) acc += g_bc_sum[b * NC + c] / (float)HW;
    float mean = acc / (float)NB;
    float a = g_rs[c] * g_qw[c];
    g_ca[c] = a;
    g_cb[c] = g_qb[c] - mean * a;
}

// ---------------- K5: out = fq(x)*a[c] + b[c] ----------------
__global__ void k_out(const float* __restrict__ x, float* __restrict__ out) {
    const int j = blockIdx.x * 256 + threadIdx.x;           // float4 index
    const float s = g_sq[0], zp = g_sq[1];
    const int c = (j >> 10) & (NC - 1);                     // 1024 float4 per (b,c)
    const float a = g_ca[c], b = g_cb[c];
    float4 v = reinterpret_cast<const float4*>(x)[j];
    float4 r;
    r.x = fmaf(fq1(v.x, s, zp), a, b);
    r.y = fmaf(fq1(v.y, s, zp), a, b);
    r.z = fmaf(fq1(v.z, s, zp), a, b);
    r.w = fmaf(fq1(v.w, s, zp), a, b);
    reinterpret_cast<float4*>(out)[j] = r;
}

// ---------------- launch ----------------
extern "C" void kernel_launch(void* const* d_in, const int* in_sizes, int n_in,
                              void* d_out, int out_size) {
    const float* x    = (const float*)d_in[0];
    const float* w    = (const float*)d_in[1];
    const float* bias = (const float*)d_in[2];
    float* out = (float*)d_out;

    k_minmax<<<NB * NC, 256>>>(x);
    k_stats<<<1, 256>>>(w, bias);
    k_sum<<<NB * NC, 256>>>(x);
    k_coef<<<1, NC>>>();
    k_out<<<(NB * NC * HW / 4) / 256, 256>>>(x, out);
}

// round 2
// speedup vs baseline: 1.4130x; 1.4130x over previous
#include <cuda_runtime.h>
#include <math.h>

#define NB 20
#define NC 256
#define HW 4096
#define NCHUNK 10
#define QMAXF 255.0f

// ---------------- device scratch ----------------
__device__ float g_bc_min[NB * NC];
__device__ float g_bc_max[NB * NC];
__device__ float g_bc_sum[NB * NC];   // sum of fq(x) per (b,c)
__device__ float g_sq[3];             // [0]=scale s, [1]=zero_point, [2]=1/s
__device__ float g_rs[NC];            // 1 / (mean_topk + 1e-7)
__device__ float g_qw[NC];            // quantized weight
__device__ float g_qb[NC];            // quantized bias

// fast fake-quant core: returns the clipped rounded quant level (integer-valued float)
__device__ __forceinline__ float qlevel(float x, float rs, float zp) {
    float v = fmaf(x, rs, zp);
    v = fminf(fmaxf(v, 0.0f), QMAXF);
    return rintf(v);              // round-half-even == jnp.round
}

// ---------------- K1: per-(b,c) raw min/max over 4096 spatial ----------------
__global__ void k_minmax(const float* __restrict__ x) {
    const int bc = blockIdx.x;
    const float4* p = reinterpret_cast<const float4*>(x) + (size_t)bc * (HW / 4);
    float mn = INFINITY, mx = -INFINITY;
    #pragma unroll
    for (int k = 0; k < 4; k++) {
        float4 v = p[threadIdx.x + k * 256];
        mn = fminf(mn, fminf(fminf(v.x, v.y), fminf(v.z, v.w)));
        mx = fmaxf(mx, fmaxf(fmaxf(v.x, v.y), fmaxf(v.z, v.w)));
    }
    #pragma unroll
    for (int o = 16; o > 0; o >>= 1) {
        mn = fminf(mn, __shfl_xor_sync(0xffffffffu, mn, o));
        mx = fmaxf(mx, __shfl_xor_sync(0xffffffffu, mx, o));
    }
    __shared__ float smn[8], smx[8];
    int wr = threadIdx.x >> 5, ln = threadIdx.x & 31;
    if (ln == 0) { smn[wr] = mn; smx[wr] = mx; }
    __syncthreads();
    if (threadIdx.x == 0) {
        float a = smn[0], b = smx[0];
        #pragma unroll
        for (int i = 1; i < 8; i++) { a = fminf(a, smn[i]); b = fmaxf(b, smx[i]); }
        g_bc_min[bc] = a;
        g_bc_max[bc] = b;
    }
}

// ---------------- K2: scalars, chunk ranges, weight/bias quant (1 block, 256 thr) ------
__global__ void k_stats(const float* __restrict__ w, const float* __restrict__ bias) {
    const int t = threadIdx.x;
    const int wr = t >> 5, ln = t & 31;
    __shared__ float sh_smin[NB], sh_smax[NB];
    __shared__ float sh_s, sh_zp, sh_rs, sh_wmin, sh_wmax, sh_bsum;

    // per-sample min/max over channels: warp wr handles samples wr, wr+8, wr+16
    for (int b = wr; b < NB; b += 8) {
        float mn = INFINITY, mx = -INFINITY;
        #pragma unroll
        for (int i = 0; i < NC / 32; i++) {
            mn = fminf(mn, g_bc_min[b * NC + i * 32 + ln]);
            mx = fmaxf(mx, g_bc_max[b * NC + i * 32 + ln]);
        }
        #pragma unroll
        for (int o = 16; o > 0; o >>= 1) {
            mn = fminf(mn, __shfl_xor_sync(0xffffffffu, mn, o));
            mx = fmaxf(mx, __shfl_xor_sync(0xffffffffu, mx, o));
        }
        if (ln == 0) { sh_smin[b] = mn; sh_smax[b] = mx; }
    }
    __syncthreads();
    if (t == 0) {
        float a = 0.f, b = 0.f;
        #pragma unroll
        for (int i = 0; i < NB; i++) { a += sh_smin[i]; b += sh_smax[i]; }
        float min_v = a / (float)NB, max_v = b / (float)NB;
        float s = (max_v - min_v) / QMAXF;
        if (s == 0.0f) s = 1.0f;
        float zp = truncf(fminf(fmaxf(__fdiv_rn(-min_v, s), 0.0f), QMAXF));
        float rs = __fdiv_rn(1.0f, s);
        sh_s = s; sh_zp = zp; sh_rs = rs;
        g_sq[0] = s; g_sq[1] = zp; g_sq[2] = rs;
    }
    __syncthreads();
    const float s = sh_s, zp = sh_zp, rs = sh_rs;

    // chunk ranges per channel (t = channel). chunk k = batches {2k, 2k+1};
    // fq is monotone so chunk min/max of xq = fq(chunk min/max of raw x).
    {
        const float cst = (float)(0.5 * 0.35 * (1.0 + sqrt(M_PI * log(4.0)))
                                  / sqrt(2.0 * log(8192.0)));   // n = 8192
        float csum = 0.f;
        #pragma unroll
        for (int k = 0; k < NCHUNK; k++) {
            float mn = fminf(g_bc_min[(2 * k) * NC + t], g_bc_min[(2 * k + 1) * NC + t]);
            float mx = fmaxf(g_bc_max[(2 * k) * NC + t], g_bc_max[(2 * k + 1) * NC + t]);
            float fmx = (qlevel(mx, rs, zp) - zp) * s;
            float fmn = (qlevel(mn, rs, zp) - zp) * s;
            csum += (fmx - fmn) * cst;
        }
        g_rs[t] = __fdiv_rn(1.0f, csum / (float)NCHUNK + 1e-7f);
    }

    // weight min/max + bias sum (256 elements, one per thread)
    float wv = w[t], bv = bias[t];
    float wmn = wv, wmx = wv, bs = bv;
    #pragma unroll
    for (int o = 16; o > 0; o >>= 1) {
        wmn = fminf(wmn, __shfl_xor_sync(0xffffffffu, wmn, o));
        wmx = fmaxf(wmx, __shfl_xor_sync(0xffffffffu, wmx, o));
        bs += __shfl_xor_sync(0xffffffffu, bs, o);
    }
    __shared__ float swmn[8], swmx[8], sbs[8];
    if (ln == 0) { swmn[wr] = wmn; swmx[wr] = wmx; sbs[wr] = bs; }
    __syncthreads();
    if (t == 0) {
        float a = swmn[0], b = swmx[0], c = sbs[0];
        #pragma unroll
        for (int i = 1; i < 8; i++) { a = fminf(a, swmn[i]); b = fmaxf(b, swmx[i]); c += sbs[i]; }
        sh_wmin = a; sh_wmax = b; sh_bsum = c;
    }
    __syncthreads();

    // quantized weight (explicit min/max) — tiny, keep IEEE div for exactness
    float ws = (sh_wmax - sh_wmin) / QMAXF;
    if (ws == 0.0f) ws = 1.0f;
    float wzp = truncf(fminf(fmaxf(__fdiv_rn(-sh_wmin, ws), 0.0f), QMAXF));
    g_qw[t] = (rintf(fminf(fmaxf(__fdiv_rn(wv, ws) + wzp, 0.0f), QMAXF)) - wzp) * ws;

    // quantized bias: min==max==bias.mean() -> scale=0 -> scale=1 branch
    float bmean = sh_bsum / (float)NC;
    float bzp = truncf(fminf(fmaxf(-bmean, 0.0f), QMAXF));
    g_qb[t] = rintf(fminf(fmaxf(bv + bzp, 0.0f), QMAXF)) - bzp;
}

// ---------------- K3: per-(b,c) sum of fq(x) via exact integer-level sum ---------------
__global__ void k_sum(const float* __restrict__ x) {
    const int bc = blockIdx.x;
    const float rs = g_sq[2], zp = g_sq[1], s = g_sq[0];
    const float4* p = reinterpret_cast<const float4*>(x) + (size_t)bc * (HW / 4);
    float acc = 0.f;   // sum of quant levels; <= 255*4096 < 2^24, exact in fp32
    #pragma unroll
    for (int k = 0; k < 4; k++) {
        float4 v = p[threadIdx.x + k * 256];
        acc += qlevel(v.x, rs, zp) + qlevel(v.y, rs, zp)
             + qlevel(v.z, rs, zp) + qlevel(v.w, rs, zp);
    }
    #pragma unroll
    for (int o = 16; o > 0; o >>= 1) acc += __shfl_xor_sync(0xffffffffu, acc, o);
    __shared__ float sm[8];
    int wr = threadIdx.x >> 5, ln = threadIdx.x & 31;
    if (ln == 0) sm[wr] = acc;
    __syncthreads();
    if (threadIdx.x == 0) {
        float a = 0.f;
        #pragma unroll
        for (int i = 0; i < 8; i++) a += sm[i];
        // sum fq = s*(sum q) - s*zp*HW
        g_bc_sum[bc] = s * a - s * zp * (float)HW;
    }
}

// ---------------- K4: out = fq(x)*a[c] + b[c], coef computed per block ----------------
__global__ void k_out(const float* __restrict__ x, float* __restrict__ out) {
    const int bc = blockIdx.x;            // one (b,c) tile of 4096 elements
    const int c = bc & (NC - 1);
    const float rs = g_sq[2], zp = g_sq[1], s = g_sq[0];

    // channel mean of xq: 20 independent uniform loads, unrolled
    float acc = 0.f;
    #pragma unroll
    for (int bb = 0; bb < NB; bb++) acc += g_bc_sum[bb * NC + c] * (1.0f / (float)HW);
    float mean = acc * (1.0f / (float)NB);
    float a = g_rs[c] * g_qw[c];
    // out = ((q - zp)*s - mean)*a + qb  =  q*(s*a) + (qb - (mean + zp*s)*a)
    float sa = s * a;
    float b2 = fmaf(-(mean + zp * s), a, g_qb[c]);

    const float4* p = reinterpret_cast<const float4*>(x) + (size_t)bc * (HW / 4);
    float4* po = reinterpret_cast<float4*>(out) + (size_t)bc * (HW / 4);
    #pragma unroll
    for (int k = 0; k < 4; k++) {
        float4 v = __ldcs(&p[threadIdx.x + k * 256]);
        float4 r;
        r.x = fmaf(qlevel(v.x, rs, zp), sa, b2);
        r.y = fmaf(qlevel(v.y, rs, zp), sa, b2);
        r.z = fmaf(qlevel(v.z, rs, zp), sa, b2);
        r.w = fmaf(qlevel(v.w, rs, zp), sa, b2);
        __stcs(&po[threadIdx.x + k * 256], r);
    }
}

// ---------------- launch ----------------
extern "C" void kernel_launch(void* const* d_in, const int* in_sizes, int n_in,
                              void* d_out, int out_size) {
    const float* x    = (const float*)d_in[0];
    const float* w    = (const float*)d_in[1];
    const float* bias = (const float*)d_in[2];
    float* out = (float*)d_out;

    k_minmax<<<NB * NC, 256>>>(x);
    k_stats<<<1, 256>>>(w, bias);
    k_sum<<<NB * NC, 256>>>(x);
    k_out<<<NB * NC, 256>>>(x, out);
}